// round 2
// baseline (speedup 1.0000x reference)
#include <cuda_runtime.h>

#define BB 64
#define TT 1024
#define CC 256
#define RREG 160
#define SROWS (CC - RREG)
#define ROWS_SM 220

__device__ float g_alpha[(size_t)BB * TT * CC];
__device__ int   g_tags[BB * TT];

__device__ __forceinline__ unsigned fkey(float v) {
    unsigned u = __float_as_uint(v);
    return (u & 0x80000000u) ? ~u : (u | 0x80000000u);
}

// Forward: one CTA/batch, thread c owns class c. Max only, no argmax.
__global__ __launch_bounds__(CC, 1)
void fwd_kernel(const float* __restrict__ seq, const float* __restrict__ trans) {
    extern __shared__ float sm[];
    float* trs   = sm;               // [SROWS][CC]
    float* albuf = sm + SROWS * CC;  // [2][CC]
    const int b = blockIdx.x, c = threadIdx.x;

    float treg[RREG];
#pragma unroll
    for (int i = 0; i < RREG; i++) treg[i] = trans[i * CC + c];
    for (int i = 0; i < SROWS; i++) trs[i * CC + c] = trans[(RREG + i) * CC + c];

    const float* sb = seq + (size_t)b * TT * CC;
    float* ab = g_alpha + (size_t)b * TT * CC;

    float a0 = sb[c];
    albuf[c] = a0;
    ab[c] = a0;
    __syncthreads();

    float emit_next = sb[CC + c];
    int cur = 0;
    for (int t = 1; t < TT; t++) {
        float emit = emit_next;
        int tn = (t + 1 < TT) ? (t + 1) : (TT - 1);
        emit_next = sb[(size_t)tn * CC + c];

        const float* as = albuf + cur * CC;
        float m0 = -3.0e38f, m1 = -3.0e38f, m2 = -3.0e38f, m3 = -3.0e38f;
#pragma unroll
        for (int p = 0; p < RREG; p += 4) {
            float4 a4 = *(const float4*)(as + p);
            m0 = fmaxf(m0, a4.x + treg[p + 0]);
            m1 = fmaxf(m1, a4.y + treg[p + 1]);
            m2 = fmaxf(m2, a4.z + treg[p + 2]);
            m3 = fmaxf(m3, a4.w + treg[p + 3]);
        }
#pragma unroll
        for (int p = 0; p < SROWS; p += 4) {
            float4 a4 = *(const float4*)(as + RREG + p);
            m0 = fmaxf(m0, a4.x + trs[(p + 0) * CC + c]);
            m1 = fmaxf(m1, a4.y + trs[(p + 1) * CC + c]);
            m2 = fmaxf(m2, a4.z + trs[(p + 2) * CC + c]);
            m3 = fmaxf(m3, a4.w + trs[(p + 3) * CC + c]);
        }
        float na = fmaxf(fmaxf(m0, m1), fmaxf(m2, m3)) + emit;
        albuf[(cur ^ 1) * CC + c] = na;
        ab[(size_t)t * CC + c] = na;
        cur ^= 1;
        __syncthreads();
    }
}

// Backward: one warp/batch; argmax recomputed only along the Viterbi path.
__global__ __launch_bounds__(32, 1)
void chase_kernel(const float* __restrict__ trans) {
    extern __shared__ float trs[];  // [ROWS_SM][CC]: trs[c][p] = trans[p][c]
    const int b = blockIdx.x, lane = threadIdx.x;

    for (int idx = lane; idx < CC * CC; idx += 32) {
        int c = idx & (CC - 1), p = idx >> 8;
        if (c < ROWS_SM) trs[c * CC + p] = trans[idx];
    }
    __syncwarp();

    const float* ab = g_alpha + (size_t)b * TT * CC;
    int* tg = g_tags + b * TT;

    int tag;
    {
        const float4* a4 = (const float4*)(ab + (size_t)(TT - 1) * CC);
        float4 x0 = a4[lane * 2], x1 = a4[lane * 2 + 1];
        unsigned k[8] = {fkey(x0.x), fkey(x0.y), fkey(x0.z), fkey(x0.w),
                         fkey(x1.x), fkey(x1.y), fkey(x1.z), fkey(x1.w)};
        unsigned m = k[0];
#pragma unroll
        for (int j = 1; j < 8; j++) m = (k[j] > m) ? k[j] : m;
        unsigned M = __reduce_max_sync(0xffffffffu, m);
        int pm = 0x7fffffff;
#pragma unroll
        for (int j = 7; j >= 0; j--) if (k[j] == M) pm = lane * 8 + j;
        tag = (int)__reduce_min_sync(0xffffffffu, (unsigned)pm);
        if (lane == 0) tg[TT - 1] = tag;
    }

    float4 c0a, c0b, c1a, c1b;
    {
        const float4* r0 = (const float4*)(ab + (size_t)(TT - 2) * CC);
        c0a = r0[lane * 2]; c0b = r0[lane * 2 + 1];
        const float4* r1 = (const float4*)(ab + (size_t)(TT - 3) * CC);
        c1a = r1[lane * 2]; c1b = r1[lane * 2 + 1];
    }

    for (int t = TT - 2; t >= 0; t--) {
        float4 xa = c0a, xb = c0b;
        c0a = c1a; c0b = c1b;
        if (t >= 2) {
            const float4* r = (const float4*)(ab + (size_t)(t - 2) * CC);
            c1a = r[lane * 2]; c1b = r[lane * 2 + 1];
        }

        float tc[8];
        if (tag < ROWS_SM) {
            const float4* r = (const float4*)(trs + tag * CC);
            float4 u0 = r[lane * 2], u1 = r[lane * 2 + 1];
            tc[0] = u0.x; tc[1] = u0.y; tc[2] = u0.z; tc[3] = u0.w;
            tc[4] = u1.x; tc[5] = u1.y; tc[6] = u1.z; tc[7] = u1.w;
        } else {
            const float* col = trans + tag;
            int p = lane * 8;
#pragma unroll
            for (int j = 0; j < 8; j++) tc[j] = col[(size_t)(p + j) * CC];
        }

        unsigned k[8] = {fkey(xa.x + tc[0]), fkey(xa.y + tc[1]),
                         fkey(xa.z + tc[2]), fkey(xa.w + tc[3]),
                         fkey(xb.x + tc[4]), fkey(xb.y + tc[5]),
                         fkey(xb.z + tc[6]), fkey(xb.w + tc[7])};
        unsigned m = k[0];
#pragma unroll
        for (int j = 1; j < 8; j++) m = (k[j] > m) ? k[j] : m;
        unsigned M = __reduce_max_sync(0xffffffffu, m);
        int pm = 0x7fffffff;
#pragma unroll
        for (int j = 7; j >= 0; j--) if (k[j] == M) pm = lane * 8 + j;
        tag = (int)__reduce_min_sync(0xffffffffu, (unsigned)pm);
        if (lane == 0) tg[t] = tag;
    }
}

// One-hot: one warp per (b,t) row.
__global__ void onehot_kernel(float* __restrict__ out) {
    int gw = (int)((blockIdx.x * (unsigned)blockDim.x + threadIdx.x) >> 5);
    int lane = threadIdx.x & 31;
    if (gw >= BB * TT) return;
    int tag = g_tags[gw];
    float4* o = (float4*)(out + (size_t)gw * CC);
    int p = lane * 8;
    float4 v0, v1;
    v0.x = (p + 0 == tag); v0.y = (p + 1 == tag);
    v0.z = (p + 2 == tag); v0.w = (p + 3 == tag);
    v1.x = (p + 4 == tag); v1.y = (p + 5 == tag);
    v1.z = (p + 6 == tag); v1.w = (p + 7 == tag);
    o[lane * 2] = v0;
    o[lane * 2 + 1] = v1;
}

extern "C" void kernel_launch(void* const* d_in, const int* in_sizes, int n_in,
                              void* d_out, int out_size) {
    const float* seq = (const float*)d_in[0];
    const float* trans = (const float*)d_in[1];
    if (n_in >= 2 && in_sizes[0] == CC * CC) {  // defensive order swap
        const float* tmp = seq; seq = trans; trans = tmp;
    }
    float* out = (float*)d_out;

    static int init = 0;
    if (!init) {
        cudaFuncSetAttribute(fwd_kernel, cudaFuncAttributeMaxDynamicSharedMemorySize,
                             (SROWS * CC + 2 * CC) * 4);
        cudaFuncSetAttribute(chase_kernel, cudaFuncAttributeMaxDynamicSharedMemorySize,
                             ROWS_SM * CC * 4);
        init = 1;
    }

    fwd_kernel<<<BB, CC, (SROWS * CC + 2 * CC) * 4>>>(seq, trans);
    chase_kernel<<<BB, 32, ROWS_SM * CC * 4>>>(trans);
    onehot_kernel<<<(BB * TT * 32 + 255) / 256, 256>>>(out);
}

// round 3
// speedup vs baseline: 1.1955x; 1.1955x over previous
#include <cuda_runtime.h>

#define BB 64
#define TT 1024
#define CC 256
#define NTH 512
#define RR 88                 // reg-resident transition rows per thread
#define SR 40                 // smem-resident transition rows per thread
#define TPAD 84               // trsT row stride in floats (80 used + 4 pad)
#define ROWS_SM 220

__device__ float g_alpha[(size_t)BB * TT * CC];

__device__ __forceinline__ unsigned fkey(float v) {
    unsigned u = __float_as_uint(v);
    return (u & 0x80000000u) ? ~u : (u | 0x80000000u);
}
__device__ __forceinline__ unsigned long long pack2(float a, float b) {
    unsigned long long r;
    asm("mov.b64 %0,{%1,%2};" : "=l"(r) : "f"(a), "f"(b));
    return r;
}
__device__ __forceinline__ unsigned long long addx2(unsigned long long a, unsigned long long b) {
    unsigned long long r;
    asm("add.rn.f32x2 %0,%1,%2;" : "=l"(r) : "l"(a), "l"(b));
    return r;
}
__device__ __forceinline__ void unpack2(unsigned long long p, float& a, float& b) {
    asm("mov.b64 {%0,%1},%2;" : "=f"(a), "=f"(b) : "l"(p));
}

// Forward: one CTA/batch, 512 threads. Thread = (class c, prev-half h).
// h=0 covers prev rows 0..127, h=1 covers 128..255. Rows [h*128, h*128+87]
// live in registers; rows [h*128+88, h*128+127] in transposed smem.
__global__ __launch_bounds__(NTH, 1)
void fwd_kernel(const float* __restrict__ seq, const float* __restrict__ trans) {
    extern __shared__ float sm[];
    float* trsT  = sm;                    // [CC][TPAD]; j<40: row 88+j, j>=40: row 216+(j-40)
    float* albuf = sm + CC * TPAD;        // [2][CC]
    float* part  = albuf + 2 * CC;        // [CC]

    const int b = blockIdx.x;
    const int tid = threadIdx.x;
    const int c = tid & (CC - 1);
    const int h = tid >> 8;               // 0 or 1
    const int rbase = h * 128;            // first prev row of this half
    const int sbase = rbase + RR;         // first smem row of this half
    const int j0 = h * SR;                // trsT column offset

    // Fill transposed smem transitions (coalesced reads).
    for (int idx = tid; idx < CC * 2 * SR; idx += NTH) {
        int jj = idx >> 8, cc = idx & (CC - 1);
        int row = (jj < SR) ? (RR + jj) : (128 + RR + (jj - SR));
        trsT[cc * TPAD + jj] = trans[row * CC + cc];
    }

    // Register transitions, packed as f32x2 pairs.
    unsigned long long treg[RR / 2];
#pragma unroll
    for (int i = 0; i < RR / 2; i++) {
        float t0 = trans[(rbase + 2 * i) * CC + c];
        float t1 = trans[(rbase + 2 * i + 1) * CC + c];
        treg[i] = pack2(t0, t1);
    }

    const float* sb = seq + (size_t)b * TT * CC;
    float* ab = g_alpha + (size_t)b * TT * CC;

    if (h == 0) {
        float a0 = sb[c];
        albuf[c] = a0;
        ab[c] = a0;
    }
    __syncthreads();

    float emit_next = (h == 0) ? sb[CC + c] : 0.0f;
    int cur = 0;
    for (int t = 1; t < TT; t++) {
        float emit = emit_next;
        if (h == 0) {
            int tn = (t + 1 < TT) ? (t + 1) : (TT - 1);
            emit_next = sb[(size_t)tn * CC + c];
        }

        const float* as = albuf + cur * CC;
        float m0 = -3.0e38f, m1 = -3.0e38f, m2 = -3.0e38f, m3 = -3.0e38f;
#pragma unroll
        for (int g = 0; g < RR / 4; g++) {
            float4 a4 = *(const float4*)(as + rbase + 4 * g);   // broadcast
            float f0, f1, f2, f3;
            unpack2(addx2(pack2(a4.x, a4.y), treg[2 * g]), f0, f1);
            unpack2(addx2(pack2(a4.z, a4.w), treg[2 * g + 1]), f2, f3);
            m0 = fmaxf(m0, f0); m1 = fmaxf(m1, f1);
            m2 = fmaxf(m2, f2); m3 = fmaxf(m3, f3);
        }
        const float* tr = trsT + c * TPAD + j0;
#pragma unroll
        for (int g = 0; g < SR / 4; g++) {
            float4 a4 = *(const float4*)(as + sbase + 4 * g);
            float4 t4 = *(const float4*)(tr + 4 * g);
            float f0, f1, f2, f3;
            unpack2(addx2(pack2(a4.x, a4.y), pack2(t4.x, t4.y)), f0, f1);
            unpack2(addx2(pack2(a4.z, a4.w), pack2(t4.z, t4.w)), f2, f3);
            m0 = fmaxf(m0, f0); m1 = fmaxf(m1, f1);
            m2 = fmaxf(m2, f2); m3 = fmaxf(m3, f3);
        }
        float m = fmaxf(fmaxf(m0, m1), fmaxf(m2, m3));
        if (h == 1) part[c] = m;
        __syncthreads();
        if (h == 0) {
            float na = fmaxf(m, part[c]) + emit;
            albuf[(cur ^ 1) * CC + c] = na;
            ab[(size_t)t * CC + c] = na;
        }
        cur ^= 1;
        __syncthreads();
    }
}

// Backward: one warp/batch; argmax recomputed only along the Viterbi path.
// Writes the one-hot output row directly as each tag resolves.
__global__ __launch_bounds__(32, 1)
void chase_kernel(const float* __restrict__ trans, float* __restrict__ out) {
    extern __shared__ float trs[];  // [ROWS_SM][CC]: trs[c][p] = trans[p][c]
    const int b = blockIdx.x, lane = threadIdx.x;

    for (int idx = lane; idx < CC * CC; idx += 32) {
        int c = idx & (CC - 1), p = idx >> 8;
        if (c < ROWS_SM) trs[c * CC + p] = trans[idx];
    }
    __syncwarp();

    const float* ab = g_alpha + (size_t)b * TT * CC;
    float* ob = out + (size_t)b * TT * CC;

    int tag;
    {
        const float4* a4 = (const float4*)(ab + (size_t)(TT - 1) * CC);
        float4 x0 = a4[lane * 2], x1 = a4[lane * 2 + 1];
        unsigned k[8] = {fkey(x0.x), fkey(x0.y), fkey(x0.z), fkey(x0.w),
                         fkey(x1.x), fkey(x1.y), fkey(x1.z), fkey(x1.w)};
        unsigned m = k[0];
#pragma unroll
        for (int j = 1; j < 8; j++) m = (k[j] > m) ? k[j] : m;
        unsigned M = __reduce_max_sync(0xffffffffu, m);
        int pm = 0x7fffffff;
#pragma unroll
        for (int j = 7; j >= 0; j--) if (k[j] == M) pm = lane * 8 + j;
        tag = (int)__reduce_min_sync(0xffffffffu, (unsigned)pm);
    }

    // one-hot writer for row t given current tag
    auto write_row = [&](int t, int tg) {
        float4* o = (float4*)(ob + (size_t)t * CC);
        int p = lane * 8;
        float4 v0, v1;
        v0.x = (p + 0 == tg); v0.y = (p + 1 == tg);
        v0.z = (p + 2 == tg); v0.w = (p + 3 == tg);
        v1.x = (p + 4 == tg); v1.y = (p + 5 == tg);
        v1.z = (p + 6 == tg); v1.w = (p + 7 == tg);
        o[lane * 2] = v0;
        o[lane * 2 + 1] = v1;
    };
    write_row(TT - 1, tag);

    float4 c0a, c0b, c1a, c1b;
    {
        const float4* r0 = (const float4*)(ab + (size_t)(TT - 2) * CC);
        c0a = r0[lane * 2]; c0b = r0[lane * 2 + 1];
        const float4* r1 = (const float4*)(ab + (size_t)(TT - 3) * CC);
        c1a = r1[lane * 2]; c1b = r1[lane * 2 + 1];
    }

    for (int t = TT - 2; t >= 0; t--) {
        float4 xa = c0a, xb = c0b;
        c0a = c1a; c0b = c1b;
        if (t >= 2) {
            const float4* r = (const float4*)(ab + (size_t)(t - 2) * CC);
            c1a = r[lane * 2]; c1b = r[lane * 2 + 1];
        }

        float tc[8];
        if (tag < ROWS_SM) {
            const float4* r = (const float4*)(trs + tag * CC);
            float4 u0 = r[lane * 2], u1 = r[lane * 2 + 1];
            tc[0] = u0.x; tc[1] = u0.y; tc[2] = u0.z; tc[3] = u0.w;
            tc[4] = u1.x; tc[5] = u1.y; tc[6] = u1.z; tc[7] = u1.w;
        } else {
            const float* col = trans + tag;
            int p = lane * 8;
#pragma unroll
            for (int j = 0; j < 8; j++) tc[j] = col[(size_t)(p + j) * CC];
        }

        unsigned k[8] = {fkey(xa.x + tc[0]), fkey(xa.y + tc[1]),
                         fkey(xa.z + tc[2]), fkey(xa.w + tc[3]),
                         fkey(xb.x + tc[4]), fkey(xb.y + tc[5]),
                         fkey(xb.z + tc[6]), fkey(xb.w + tc[7])};
        unsigned m = k[0];
#pragma unroll
        for (int j = 1; j < 8; j++) m = (k[j] > m) ? k[j] : m;
        unsigned M = __reduce_max_sync(0xffffffffu, m);
        int pm = 0x7fffffff;
#pragma unroll
        for (int j = 7; j >= 0; j--) if (k[j] == M) pm = lane * 8 + j;
        tag = (int)__reduce_min_sync(0xffffffffu, (unsigned)pm);
        write_row(t, tag);
    }
}

extern "C" void kernel_launch(void* const* d_in, const int* in_sizes, int n_in,
                              void* d_out, int out_size) {
    const float* seq = (const float*)d_in[0];
    const float* trans = (const float*)d_in[1];
    if (n_in >= 2 && in_sizes[0] == CC * CC) {  // defensive order swap
        const float* tmp = seq; seq = trans; trans = tmp;
    }
    float* out = (float*)d_out;

    const int fwd_smem = (CC * TPAD + 3 * CC) * 4;
    static int init = 0;
    if (!init) {
        cudaFuncSetAttribute(fwd_kernel, cudaFuncAttributeMaxDynamicSharedMemorySize, fwd_smem);
        cudaFuncSetAttribute(chase_kernel, cudaFuncAttributeMaxDynamicSharedMemorySize,
                             ROWS_SM * CC * 4);
        init = 1;
    }

    fwd_kernel<<<BB, NTH, fwd_smem>>>(seq, trans);
    chase_kernel<<<BB, 32, ROWS_SM * CC * 4>>>(trans, out);
}